// round 1
// baseline (speedup 1.0000x reference)
#include <cuda_runtime.h>
#include <math.h>

#define B_ 2
#define N_ 2048
#define C_ 1024
#define H_ 16
#define D_ 64
#define F_ 4096
#define M_ (B_*N_)   // 4096 rows

// ---------------- scratch (static device globals; no runtime allocation) ----
__device__ float g_h  [M_*C_];
__device__ float g_q  [M_*C_];   // (B,H,N,D)
__device__ float g_k  [M_*C_];   // (B,H,N,D)
__device__ float g_v  [M_*C_];   // (B,H,N,D)
__device__ float g_ao [M_*C_];   // attention out, (B,N,C)
__device__ float g_x1 [M_*C_];   // residual after attention
__device__ float g_h2 [M_*C_];
__device__ float g_mlp[M_*F_];

// ---------------- LayerNorm: one block per row of 1024 ----------------------
__global__ void ln_kernel(const float* __restrict__ x,
                          const float* __restrict__ g,
                          const float* __restrict__ b,
                          float* __restrict__ out)
{
    int row = blockIdx.x;
    int t = threadIdx.x;                       // 256 threads, 4 floats each
    const float4* xr = (const float4*)(x + (size_t)row * C_);
    float4 xv = xr[t];

    float s  = xv.x + xv.y + xv.z + xv.w;
    float sq = xv.x*xv.x + xv.y*xv.y + xv.z*xv.z + xv.w*xv.w;

    #pragma unroll
    for (int o = 16; o > 0; o >>= 1) {
        s  += __shfl_xor_sync(0xffffffffu, s,  o);
        sq += __shfl_xor_sync(0xffffffffu, sq, o);
    }
    __shared__ float rs[8], rq[8];
    if ((t & 31) == 0) { rs[t >> 5] = s; rq[t >> 5] = sq; }
    __syncthreads();
    __shared__ float s_mean, s_rstd;
    if (t == 0) {
        float ts = 0.f, tq = 0.f;
        #pragma unroll
        for (int i = 0; i < 8; i++) { ts += rs[i]; tq += rq[i]; }
        float mean = ts / (float)C_;
        float var  = tq / (float)C_ - mean * mean;
        s_mean = mean;
        s_rstd = rsqrtf(var + 1e-6f);
    }
    __syncthreads();
    float mean = s_mean, rstd = s_rstd;

    float4 gv = ((const float4*)g)[t];
    float4 bv = ((const float4*)b)[t];
    float4 ov;
    ov.x = (xv.x - mean) * rstd * gv.x + bv.x;
    ov.y = (xv.y - mean) * rstd * gv.y + bv.y;
    ov.z = (xv.z - mean) * rstd * gv.z + bv.z;
    ov.w = (xv.w - mean) * rstd * gv.w + bv.w;
    ((float4*)(out + (size_t)row * C_))[t] = ov;
}

// ---------------- Generic NT SGEMM: C[M,N] = A[M,K] @ B[N,K]^T + epilogue ----
// EPI: 0 = bias, 1 = bias + residual, 2 = bias + exact GELU,
//      3 = bias + permuted store to (B,H,N,D)
template<int EPI>
__global__ void __launch_bounds__(256)
gemm_nt(const float* __restrict__ A, const float* __restrict__ Bm,
        const float* __restrict__ bias, float* __restrict__ Cout,
        const float* __restrict__ Res, int M, int N, int K)
{
    const int BK = 16;
    __shared__ __align__(16) float As[BK * 132];
    __shared__ __align__(16) float Bs[BK * 132];

    int tid = threadIdx.x;
    int tx = tid & 15;          // 0..15 -> 8 cols each
    int ty = tid >> 4;          // 0..15 -> 8 rows each
    int m0 = blockIdx.y * 128;
    int n0 = blockIdx.x * 128;

    float acc[8][8];
    #pragma unroll
    for (int i = 0; i < 8; i++)
        #pragma unroll
        for (int j = 0; j < 8; j++) acc[i][j] = 0.f;

    for (int k0 = 0; k0 < K; k0 += BK) {
        __syncthreads();
        #pragma unroll
        for (int l = 0; l < 2; l++) {
            int idx = tid + l * 256;            // 0..511
            int row = idx >> 2;                 // 0..127
            int kq  = (idx & 3) << 2;           // 0,4,8,12
            float4 av = *(const float4*)(A + (size_t)(m0 + row) * K + k0 + kq);
            As[(kq + 0) * 132 + row] = av.x;
            As[(kq + 1) * 132 + row] = av.y;
            As[(kq + 2) * 132 + row] = av.z;
            As[(kq + 3) * 132 + row] = av.w;
            float4 bv = *(const float4*)(Bm + (size_t)(n0 + row) * K + k0 + kq);
            Bs[(kq + 0) * 132 + row] = bv.x;
            Bs[(kq + 1) * 132 + row] = bv.y;
            Bs[(kq + 2) * 132 + row] = bv.z;
            Bs[(kq + 3) * 132 + row] = bv.w;
        }
        __syncthreads();

        #pragma unroll
        for (int kk = 0; kk < BK; kk++) {
            float a[8], b[8];
            *(float4*)&a[0] = *(const float4*)&As[kk * 132 + ty * 8];
            *(float4*)&a[4] = *(const float4*)&As[kk * 132 + ty * 8 + 4];
            *(float4*)&b[0] = *(const float4*)&Bs[kk * 132 + tx * 8];
            *(float4*)&b[4] = *(const float4*)&Bs[kk * 132 + tx * 8 + 4];
            #pragma unroll
            for (int i = 0; i < 8; i++)
                #pragma unroll
                for (int j = 0; j < 8; j++)
                    acc[i][j] = fmaf(a[i], b[j], acc[i][j]);
        }
    }

    #pragma unroll
    for (int i = 0; i < 8; i++) {
        int m = m0 + ty * 8 + i;
        #pragma unroll
        for (int j = 0; j < 8; j++) {
            int n = n0 + tx * 8 + j;
            float val = acc[i][j] + bias[n];
            if (EPI == 0) {
                Cout[(size_t)m * N + n] = val;
            } else if (EPI == 1) {
                Cout[(size_t)m * N + n] = val + Res[(size_t)m * N + n];
            } else if (EPI == 2) {
                val = 0.5f * val * (1.0f + erff(val * 0.70710678118654752f));
                Cout[(size_t)m * N + n] = val;
            } else { // EPI == 3: permute (B*N, H*D) -> (B,H,N,D)
                int bb  = m >> 11;       // m / N_
                int pos = m & (N_ - 1);
                int hh  = n >> 6;        // n / D_
                int dd  = n & (D_ - 1);
                Cout[(((size_t)(bb * H_ + hh)) * N_ + pos) * D_ + dd] = val;
            }
        }
    }
}

// ---------------- RoPE in place on q and k (B,H,N,D) -------------------------
__global__ void rope_kernel(float* __restrict__ q, float* __restrict__ k,
                            const float* __restrict__ cosb,
                            const float* __restrict__ sinb)
{
    int idx = blockIdx.x * blockDim.x + threadIdx.x;   // B*H*N*32 threads
    int d  = idx & 31;
    int n  = (idx >> 5) & (N_ - 1);
    int bh = idx >> 16;                                 // 2048*32 = 2^16 per bh

    float c1 = cosb[n * D_ + d],      s1 = sinb[n * D_ + d];
    float c2 = cosb[n * D_ + d + 32], s2 = sinb[n * D_ + d + 32];
    size_t base = ((size_t)bh * N_ + n) * D_;

    float q1 = q[base + d], q2 = q[base + d + 32];
    q[base + d]      = q1 * c1 - q2 * s1;
    q[base + d + 32] = q2 * c2 + q1 * s2;

    float k1 = k[base + d], k2 = k[base + d + 32];
    k[base + d]      = k1 * c1 - k2 * s1;
    k[base + d + 32] = k2 * c2 + k1 * s2;
}

// ---------------- Flash attention: 128 q rows / block, 64-key tiles ----------
// smem layout (floats): qs[128*65] | kst[64*68] | vs[64*68] | ps[128*68]
#define QS_OFF 0
#define KT_OFF (128*65)
#define VS_OFF (KT_OFF + 64*68)
#define PS_OFF (VS_OFF + 64*68)
#define ATTN_SMEM_FLOATS (PS_OFF + 128*68)
#define ATTN_SMEM_BYTES  (ATTN_SMEM_FLOATS * 4)

__global__ void __launch_bounds__(256, 2)
attn_kernel(const float* __restrict__ q, const float* __restrict__ k,
            const float* __restrict__ v, float* __restrict__ out)
{
    extern __shared__ float sm[];
    float* qs  = sm + QS_OFF;   // [r][kk] stride 65
    float* kst = sm + KT_OFF;   // [kk][c] stride 68 (transposed K tile)
    float* vs  = sm + VS_OFF;   // [c][d]  stride 68
    float* ps  = sm + PS_OFF;   // [r][c]  stride 68

    int bh = blockIdx.y;                  // b*H + h
    int q0 = blockIdx.x * 128;
    const float* qb = q + (size_t)bh * N_ * D_;
    const float* kb = k + (size_t)bh * N_ * D_;
    const float* vb = v + (size_t)bh * N_ * D_;

    int t   = threadIdx.x;
    int g   = t >> 2;          // 0..63 : row group
    int sub = t & 3;           // 0..3  : 16-col / 16-dim slice
    int r0 = g, r1 = g + 64;
    int c0 = sub * 16;

    // load Q tile
    for (int i = t; i < 128 * 64; i += 256) {
        int rr = i >> 6, dd = i & 63;
        qs[rr * 65 + dd] = qb[(size_t)(q0 + rr) * D_ + dd];
    }

    float m0s = -1e30f, m1s = -1e30f, l0s = 0.f, l1s = 0.f;
    float o0[16], o1[16];
    #pragma unroll
    for (int i = 0; i < 16; i++) { o0[i] = 0.f; o1[i] = 0.f; }

    const float scale = 0.125f;   // D^-0.5

    for (int kt = 0; kt < N_; kt += 64) {
        __syncthreads();   // previous tile's AV reads done
        for (int i = t; i < 64 * 64; i += 256) {
            int rr = i >> 6, dd = i & 63;
            float kv = kb[(size_t)(kt + rr) * D_ + dd];
            kst[dd * 68 + rr] = kv;
            vs[rr * 68 + dd]  = vb[(size_t)(kt + rr) * D_ + dd];
        }
        __syncthreads();

        // scores: 2 rows x 16 cols per thread
        float s0[16], s1[16];
        #pragma unroll
        for (int j = 0; j < 16; j++) { s0[j] = 0.f; s1[j] = 0.f; }
        #pragma unroll 4
        for (int kk = 0; kk < 64; kk++) {
            float qv0 = qs[r0 * 65 + kk];
            float qv1 = qs[r1 * 65 + kk];
            float kvv[16];
            *(float4*)&kvv[0]  = *(const float4*)&kst[kk * 68 + c0];
            *(float4*)&kvv[4]  = *(const float4*)&kst[kk * 68 + c0 + 4];
            *(float4*)&kvv[8]  = *(const float4*)&kst[kk * 68 + c0 + 8];
            *(float4*)&kvv[12] = *(const float4*)&kst[kk * 68 + c0 + 12];
            #pragma unroll
            for (int j = 0; j < 16; j++) {
                s0[j] = fmaf(qv0, kvv[j], s0[j]);
                s1[j] = fmaf(qv1, kvv[j], s1[j]);
            }
        }

        // online softmax
        float mt0 = -1e30f, mt1 = -1e30f;
        #pragma unroll
        for (int j = 0; j < 16; j++) {
            s0[j] *= scale; s1[j] *= scale;
            mt0 = fmaxf(mt0, s0[j]); mt1 = fmaxf(mt1, s1[j]);
        }
        mt0 = fmaxf(mt0, __shfl_xor_sync(0xffffffffu, mt0, 1));
        mt0 = fmaxf(mt0, __shfl_xor_sync(0xffffffffu, mt0, 2));
        mt1 = fmaxf(mt1, __shfl_xor_sync(0xffffffffu, mt1, 1));
        mt1 = fmaxf(mt1, __shfl_xor_sync(0xffffffffu, mt1, 2));

        float mn0 = fmaxf(m0s, mt0), mn1 = fmaxf(m1s, mt1);
        float cr0 = __expf(m0s - mn0), cr1 = __expf(m1s - mn1);
        float ls0 = 0.f, ls1 = 0.f;
        #pragma unroll
        for (int j = 0; j < 16; j++) {
            float p0 = __expf(s0[j] - mn0);
            float p1 = __expf(s1[j] - mn1);
            ps[r0 * 68 + c0 + j] = p0;
            ps[r1 * 68 + c0 + j] = p1;
            ls0 += p0; ls1 += p1;
        }
        ls0 += __shfl_xor_sync(0xffffffffu, ls0, 1);
        ls0 += __shfl_xor_sync(0xffffffffu, ls0, 2);
        ls1 += __shfl_xor_sync(0xffffffffu, ls1, 1);
        ls1 += __shfl_xor_sync(0xffffffffu, ls1, 2);
        l0s = l0s * cr0 + ls0;  m0s = mn0;
        l1s = l1s * cr1 + ls1;  m1s = mn1;
        #pragma unroll
        for (int i = 0; i < 16; i++) { o0[i] *= cr0; o1[i] *= cr1; }

        __syncthreads();   // ps complete

        // AV: accumulate 16 dims (c0..c0+15) over all 64 cols
        #pragma unroll 4
        for (int c = 0; c < 64; c++) {
            float p0 = ps[r0 * 68 + c];
            float p1 = ps[r1 * 68 + c];
            float vv[16];
            *(float4*)&vv[0]  = *(const float4*)&vs[c * 68 + c0];
            *(float4*)&vv[4]  = *(const float4*)&vs[c * 68 + c0 + 4];
            *(float4*)&vv[8]  = *(const float4*)&vs[c * 68 + c0 + 8];
            *(float4*)&vv[12] = *(const float4*)&vs[c * 68 + c0 + 12];
            #pragma unroll
            for (int dd = 0; dd < 16; dd++) {
                o0[dd] = fmaf(p0, vv[dd], o0[dd]);
                o1[dd] = fmaf(p1, vv[dd], o1[dd]);
            }
        }
    }

    // write out to (B, N, H*D)
    int bb = bh >> 4, hh = bh & 15;
    float inv0 = 1.0f / l0s, inv1 = 1.0f / l1s;
    size_t base0 = ((size_t)(bb * N_ + q0 + r0)) * C_ + hh * 64 + c0;
    size_t base1 = ((size_t)(bb * N_ + q0 + r1)) * C_ + hh * 64 + c0;
    #pragma unroll
    for (int dd = 0; dd < 16; dd++) {
        out[base0 + dd] = o0[dd] * inv0;
        out[base1 + dd] = o1[dd] * inv1;
    }
}

// ---------------- launch ----------------------------------------------------
extern "C" void kernel_launch(void* const* d_in, const int* in_sizes, int n_in,
                              void* d_out, int out_size)
{
    const float* x     = (const float*)d_in[0];
    const float* rcos  = (const float*)d_in[1];
    const float* rsin  = (const float*)d_in[2];
    const float* ln1g  = (const float*)d_in[3];
    const float* ln1b  = (const float*)d_in[4];
    const float* Wq    = (const float*)d_in[5];
    const float* bq    = (const float*)d_in[6];
    const float* Wk    = (const float*)d_in[7];
    const float* bk    = (const float*)d_in[8];
    const float* Wv    = (const float*)d_in[9];
    const float* bv    = (const float*)d_in[10];
    const float* Wo    = (const float*)d_in[11];
    const float* bo    = (const float*)d_in[12];
    const float* ln2g  = (const float*)d_in[13];
    const float* ln2b  = (const float*)d_in[14];
    const float* W1    = (const float*)d_in[15];
    const float* b1    = (const float*)d_in[16];
    const float* W2    = (const float*)d_in[17];
    const float* b2    = (const float*)d_in[18];
    float* out = (float*)d_out;

    float *ph, *pq, *pk, *pv, *pao, *px1, *ph2, *pmlp;
    cudaGetSymbolAddress((void**)&ph,   g_h);
    cudaGetSymbolAddress((void**)&pq,   g_q);
    cudaGetSymbolAddress((void**)&pk,   g_k);
    cudaGetSymbolAddress((void**)&pv,   g_v);
    cudaGetSymbolAddress((void**)&pao,  g_ao);
    cudaGetSymbolAddress((void**)&px1,  g_x1);
    cudaGetSymbolAddress((void**)&ph2,  g_h2);
    cudaGetSymbolAddress((void**)&pmlp, g_mlp);

    cudaFuncSetAttribute(attn_kernel,
        cudaFuncAttributeMaxDynamicSharedMemorySize, ATTN_SMEM_BYTES);

    // 1. LN1
    ln_kernel<<<M_, 256>>>(x, ln1g, ln1b, ph);

    // 2. QKV projections (epilogue permutes to (B,H,N,D))
    dim3 gqkv(C_ / 128, M_ / 128);
    gemm_nt<3><<<gqkv, 256>>>(ph, Wq, bq, pq, nullptr, M_, C_, C_);
    gemm_nt<3><<<gqkv, 256>>>(ph, Wk, bk, pk, nullptr, M_, C_, C_);
    gemm_nt<3><<<gqkv, 256>>>(ph, Wv, bv, pv, nullptr, M_, C_, C_);

    // 3. RoPE on q, k
    rope_kernel<<<(B_ * H_ * N_ * 32) / 256, 256>>>(pq, pk, rcos, rsin);

    // 4. Attention
    attn_kernel<<<dim3(N_ / 128, B_ * H_), 256, ATTN_SMEM_BYTES>>>(pq, pk, pv, pao);

    // 5. O projection + residual -> x1
    gemm_nt<1><<<gqkv, 256>>>(pao, Wo, bo, px1, x, M_, C_, C_);

    // 6. LN2
    ln_kernel<<<M_, 256>>>(px1, ln2g, ln2b, ph2);

    // 7. MLP up + GELU
    dim3 gup(F_ / 128, M_ / 128);
    gemm_nt<2><<<gup, 256>>>(ph2, W1, b1, pmlp, nullptr, M_, F_, C_);

    // 8. MLP down + residual -> out
    dim3 gdn(C_ / 128, M_ / 128);
    gemm_nt<1><<<gdn, 256>>>(pmlp, W2, b2, out, px1, M_, C_, F_);
}

// round 3
// speedup vs baseline: 1.4994x; 1.4994x over previous
#include <cuda_runtime.h>
#include <math.h>
#include <stdint.h>

#define B_ 2
#define N_ 2048
#define C_ 1024
#define H_ 16
#define D_ 64
#define F_ 4096
#define M_ (B_*N_)   // 4096 rows

// ---------------- scratch ----------------------------------------------------
__device__ float g_h  [M_*C_];
__device__ float g_q  [M_*C_];   // (B,H,N,D)
__device__ float g_k  [M_*C_];   // (B,H,N,D)
__device__ float g_v  [M_*C_];   // (B,H,N,D)
__device__ float g_ao [M_*C_];   // attention out, (B,N,C)
__device__ float g_x1 [M_*C_];   // residual after attention
__device__ float g_h2 [M_*C_];
__device__ float g_mlp[M_*F_];

// ---------------- helpers ----------------------------------------------------
__device__ __forceinline__ uint32_t f2tf(float f) {
    uint32_t r;
    asm("cvt.rna.tf32.f32 %0, %1;" : "=r"(r) : "f"(f));
    return r;
}

__device__ __forceinline__ void mma_tf32(float* d, const uint32_t* a,
                                         const uint32_t* b) {
    asm volatile(
        "mma.sync.aligned.m16n8k8.row.col.f32.tf32.tf32.f32 "
        "{%0,%1,%2,%3}, {%4,%5,%6,%7}, {%8,%9}, {%0,%1,%2,%3};"
        : "+f"(d[0]), "+f"(d[1]), "+f"(d[2]), "+f"(d[3])
        : "r"(a[0]), "r"(a[1]), "r"(a[2]), "r"(a[3]),
          "r"(b[0]), "r"(b[1]));
}

// ---------------- LayerNorm --------------------------------------------------
__global__ void ln_kernel(const float* __restrict__ x,
                          const float* __restrict__ g,
                          const float* __restrict__ b,
                          float* __restrict__ out)
{
    int row = blockIdx.x;
    int t = threadIdx.x;
    const float4* xr = (const float4*)(x + (size_t)row * C_);
    float4 xv = xr[t];

    float s  = xv.x + xv.y + xv.z + xv.w;
    float sq = xv.x*xv.x + xv.y*xv.y + xv.z*xv.z + xv.w*xv.w;
    #pragma unroll
    for (int o = 16; o > 0; o >>= 1) {
        s  += __shfl_xor_sync(0xffffffffu, s,  o);
        sq += __shfl_xor_sync(0xffffffffu, sq, o);
    }
    __shared__ float rs[8], rq[8];
    if ((t & 31) == 0) { rs[t >> 5] = s; rq[t >> 5] = sq; }
    __syncthreads();
    __shared__ float s_mean, s_rstd;
    if (t == 0) {
        float ts = 0.f, tq = 0.f;
        #pragma unroll
        for (int i = 0; i < 8; i++) { ts += rs[i]; tq += rq[i]; }
        float mean = ts / (float)C_;
        float var  = tq / (float)C_ - mean * mean;
        s_mean = mean; s_rstd = rsqrtf(var + 1e-6f);
    }
    __syncthreads();
    float mean = s_mean, rstd = s_rstd;
    float4 gv = ((const float4*)g)[t];
    float4 bv = ((const float4*)b)[t];
    float4 ov;
    ov.x = (xv.x - mean) * rstd * gv.x + bv.x;
    ov.y = (xv.y - mean) * rstd * gv.y + bv.y;
    ov.z = (xv.z - mean) * rstd * gv.z + bv.z;
    ov.w = (xv.w - mean) * rstd * gv.w + bv.w;
    ((float4*)(out + (size_t)row * C_))[t] = ov;
}

// ---------------- tf32 mma.sync GEMM: C[M,N] = A[M,K] @ B[N,K]^T -------------
// EPI: 0 = bias, 1 = bias + residual, 2 = bias + exact GELU,
//      3 = bias + permuted store to (B,H,N,D)
// CTA tile 128x128, BK=32, 8 warps (2 m x 4 n), warp tile 64x32, m16n8k8.
#define LDS_ (36)   // row stride in 32-bit words (pad 4 -> conflict-free frags)

template<int EPI>
__global__ void __launch_bounds__(256, 1)
mma_gemm(const float* __restrict__ A, const float* __restrict__ Bm,
         const float* __restrict__ bias, float* __restrict__ Cout,
         const float* __restrict__ Res, int M, int N, int K)
{
    __shared__ __align__(16) uint32_t As[128 * LDS_];
    __shared__ __align__(16) uint32_t Bs[128 * LDS_];

    int tid  = threadIdx.x;
    int lane = tid & 31;
    int g    = lane >> 2;       // groupID 0..7
    int q    = lane & 3;        // threadID_in_group 0..3
    int wid  = tid >> 5;
    int mbase = (wid & 1) * 64;
    int nbase = (wid >> 1) * 32;
    int m0 = blockIdx.y * 128;
    int n0 = blockIdx.x * 128;

    float acc[4][4][4];
    #pragma unroll
    for (int im = 0; im < 4; im++)
        #pragma unroll
        for (int in_ = 0; in_ < 4; in_++)
            #pragma unroll
            for (int e = 0; e < 4; e++) acc[im][in_][e] = 0.f;

    // per-thread load slots: 4 float4 from A, 4 from B per k-tile
    int lrow[4], lq[4];
    #pragma unroll
    for (int l = 0; l < 4; l++) {
        int idx = tid + l * 256;       // 0..1023
        lrow[l] = idx >> 3;            // 0..127
        lq[l]   = idx & 7;             // float4 slot in 32-float row
    }

    float4 pa[4], pb[4];
    #pragma unroll
    for (int l = 0; l < 4; l++) {
        pa[l] = *(const float4*)(A + (size_t)(m0 + lrow[l]) * K + lq[l] * 4);
        pb[l] = *(const float4*)(Bm + (size_t)(n0 + lrow[l]) * K + lq[l] * 4);
    }

    const int iters = K >> 5;
    for (int i = 0; i < iters; i++) {
        __syncthreads();   // previous compute done before overwrite
        #pragma unroll
        for (int l = 0; l < 4; l++) {
            uint4 va = make_uint4(f2tf(pa[l].x), f2tf(pa[l].y),
                                  f2tf(pa[l].z), f2tf(pa[l].w));
            *(uint4*)&As[lrow[l] * LDS_ + lq[l] * 4] = va;
            uint4 vb = make_uint4(f2tf(pb[l].x), f2tf(pb[l].y),
                                  f2tf(pb[l].z), f2tf(pb[l].w));
            *(uint4*)&Bs[lrow[l] * LDS_ + lq[l] * 4] = vb;
        }
        __syncthreads();

        if (i + 1 < iters) {
            int k0 = (i + 1) << 5;
            #pragma unroll
            for (int l = 0; l < 4; l++) {
                pa[l] = *(const float4*)(A + (size_t)(m0 + lrow[l]) * K + k0 + lq[l] * 4);
                pb[l] = *(const float4*)(Bm + (size_t)(n0 + lrow[l]) * K + k0 + lq[l] * 4);
            }
        }

        #pragma unroll
        for (int ks = 0; ks < 4; ks++) {
            uint32_t af[4][4], bf[4][2];
            int kc = ks * 8 + q;
            #pragma unroll
            for (int im = 0; im < 4; im++) {
                int r = (mbase + im * 16 + g) * LDS_;
                af[im][0] = As[r + kc];
                af[im][1] = As[r + 8 * LDS_ + kc];
                af[im][2] = As[r + kc + 4];
                af[im][3] = As[r + 8 * LDS_ + kc + 4];
            }
            #pragma unroll
            for (int in_ = 0; in_ < 4; in_++) {
                int r = (nbase + in_ * 8 + g) * LDS_;
                bf[in_][0] = Bs[r + kc];
                bf[in_][1] = Bs[r + kc + 4];
            }
            #pragma unroll
            for (int im = 0; im < 4; im++)
                #pragma unroll
                for (int in_ = 0; in_ < 4; in_++)
                    mma_tf32(acc[im][in_], af[im], bf[in_]);
        }
    }

    // ---------------- epilogue (acc in registers) ----------------
    #pragma unroll
    for (int im = 0; im < 4; im++) {
        int mrow0 = m0 + mbase + im * 16 + g;
        #pragma unroll
        for (int in_ = 0; in_ < 4; in_++) {
            int n = n0 + nbase + in_ * 8 + 2 * q;
            float b0 = bias[n], b1 = bias[n + 1];
            #pragma unroll
            for (int half = 0; half < 2; half++) {
                int m = mrow0 + half * 8;
                float v0 = acc[im][in_][half * 2 + 0] + b0;
                float v1 = acc[im][in_][half * 2 + 1] + b1;
                if (EPI == 1) {
                    float2 rr = *(const float2*)(Res + (size_t)m * N + n);
                    v0 += rr.x; v1 += rr.y;
                } else if (EPI == 2) {
                    v0 = 0.5f * v0 * (1.0f + erff(v0 * 0.70710678118654752f));
                    v1 = 0.5f * v1 * (1.0f + erff(v1 * 0.70710678118654752f));
                }
                float2 ov = make_float2(v0, v1);
                if (EPI == 3) {
                    int bb  = m >> 11;
                    int pos = m & (N_ - 1);
                    int hh  = n >> 6;
                    int dd  = n & (D_ - 1);
                    *(float2*)(Cout + (((size_t)(bb * H_ + hh)) * N_ + pos) * D_ + dd) = ov;
                } else {
                    *(float2*)(Cout + (size_t)m * N + n) = ov;
                }
            }
        }
    }
}

// ---------------- RoPE -------------------------------------------------------
__global__ void rope_kernel(float* __restrict__ q, float* __restrict__ k,
                            const float* __restrict__ cosb,
                            const float* __restrict__ sinb)
{
    int idx = blockIdx.x * blockDim.x + threadIdx.x;
    int d  = idx & 31;
    int n  = (idx >> 5) & (N_ - 1);
    int bh = idx >> 16;

    float c1 = cosb[n * D_ + d],      s1 = sinb[n * D_ + d];
    float c2 = cosb[n * D_ + d + 32], s2 = sinb[n * D_ + d + 32];
    size_t base = ((size_t)bh * N_ + n) * D_;

    float q1 = q[base + d], q2 = q[base + d + 32];
    q[base + d]      = q1 * c1 - q2 * s1;
    q[base + d + 32] = q2 * c2 + q1 * s2;

    float k1 = k[base + d], k2 = k[base + d + 32];
    k[base + d]      = k1 * c1 - k2 * s1;
    k[base + d + 32] = k2 * c2 + k1 * s2;
}

// ---------------- Flash attention (SIMT) -------------------------------------
#define QS_OFF 0
#define KT_OFF (128*65)
#define VS_OFF (KT_OFF + 64*68)
#define PS_OFF (VS_OFF + 64*68)
#define ATTN_SMEM_FLOATS (PS_OFF + 128*68)
#define ATTN_SMEM_BYTES  (ATTN_SMEM_FLOATS * 4)

__global__ void __launch_bounds__(256, 2)
attn_kernel(const float* __restrict__ q, const float* __restrict__ k,
            const float* __restrict__ v, float* __restrict__ out)
{
    extern __shared__ float sm[];
    float* qs  = sm + QS_OFF;
    float* kst = sm + KT_OFF;
    float* vs  = sm + VS_OFF;
    float* ps  = sm + PS_OFF;

    int bh = blockIdx.y;
    int q0 = blockIdx.x * 128;
    const float* qb = q + (size_t)bh * N_ * D_;
    const float* kb = k + (size_t)bh * N_ * D_;
    const float* vb = v + (size_t)bh * N_ * D_;

    int t   = threadIdx.x;
    int g   = t >> 2;
    int sub = t & 3;
    int r0 = g, r1 = g + 64;
    int c0 = sub * 16;

    for (int i = t; i < 128 * 64; i += 256) {
        int rr = i >> 6, dd = i & 63;
        qs[rr * 65 + dd] = qb[(size_t)(q0 + rr) * D_ + dd];
    }

    float m0s = -1e30f, m1s = -1e30f, l0s = 0.f, l1s = 0.f;
    float o0[16], o1[16];
    #pragma unroll
    for (int i = 0; i < 16; i++) { o0[i] = 0.f; o1[i] = 0.f; }

    const float scale = 0.125f;

    for (int kt = 0; kt < N_; kt += 64) {
        __syncthreads();
        for (int i = t; i < 64 * 64; i += 256) {
            int rr = i >> 6, dd = i & 63;
            float kv = kb[(size_t)(kt + rr) * D_ + dd];
            kst[dd * 68 + rr] = kv;
            vs[rr * 68 + dd]  = vb[(size_t)(kt + rr) * D_ + dd];
        }
        __syncthreads();

        float s0[16], s1[16];
        #pragma unroll
        for (int j = 0; j < 16; j++) { s0[j] = 0.f; s1[j] = 0.f; }
        #pragma unroll 4
        for (int kk = 0; kk < 64; kk++) {
            float qv0 = qs[r0 * 65 + kk];
            float qv1 = qs[r1 * 65 + kk];
            float kvv[16];
            *(float4*)&kvv[0]  = *(const float4*)&kst[kk * 68 + c0];
            *(float4*)&kvv[4]  = *(const float4*)&kst[kk * 68 + c0 + 4];
            *(float4*)&kvv[8]  = *(const float4*)&kst[kk * 68 + c0 + 8];
            *(float4*)&kvv[12] = *(const float4*)&kst[kk * 68 + c0 + 12];
            #pragma unroll
            for (int j = 0; j < 16; j++) {
                s0[j] = fmaf(qv0, kvv[j], s0[j]);
                s1[j] = fmaf(qv1, kvv[j], s1[j]);
            }
        }

        float mt0 = -1e30f, mt1 = -1e30f;
        #pragma unroll
        for (int j = 0; j < 16; j++) {
            s0[j] *= scale; s1[j] *= scale;
            mt0 = fmaxf(mt0, s0[j]); mt1 = fmaxf(mt1, s1[j]);
        }
        mt0 = fmaxf(mt0, __shfl_xor_sync(0xffffffffu, mt0, 1));
        mt0 = fmaxf(mt0, __shfl_xor_sync(0xffffffffu, mt0, 2));
        mt1 = fmaxf(mt1, __shfl_xor_sync(0xffffffffu, mt1, 1));
        mt1 = fmaxf(mt1, __shfl_xor_sync(0xffffffffu, mt1, 2));

        float mn0 = fmaxf(m0s, mt0), mn1 = fmaxf(m1s, mt1);
        float cr0 = __expf(m0s - mn0), cr1 = __expf(m1s - mn1);
        float ls0 = 0.f, ls1 = 0.f;
        #pragma unroll
        for (int j = 0; j < 16; j++) {
            float p0 = __expf(s0[j] - mn0);
            float p1 = __expf(s1[j] - mn1);
            ps[r0 * 68 + c0 + j] = p0;
            ps[r1 * 68 + c0 + j] = p1;
            ls0 += p0; ls1 += p1;
        }
        ls0 += __shfl_xor_sync(0xffffffffu, ls0, 1);
        ls0 += __shfl_xor_sync(0xffffffffu, ls0, 2);
        ls1 += __shfl_xor_sync(0xffffffffu, ls1, 1);
        ls1 += __shfl_xor_sync(0xffffffffu, ls1, 2);
        l0s = l0s * cr0 + ls0;  m0s = mn0;
        l1s = l1s * cr1 + ls1;  m1s = mn1;
        #pragma unroll
        for (int i = 0; i < 16; i++) { o0[i] *= cr0; o1[i] *= cr1; }

        __syncthreads();

        #pragma unroll 4
        for (int c = 0; c < 64; c++) {
            float p0 = ps[r0 * 68 + c];
            float p1 = ps[r1 * 68 + c];
            float vv[16];
            *(float4*)&vv[0]  = *(const float4*)&vs[c * 68 + c0];
            *(float4*)&vv[4]  = *(const float4*)&vs[c * 68 + c0 + 4];
            *(float4*)&vv[8]  = *(const float4*)&vs[c * 68 + c0 + 8];
            *(float4*)&vv[12] = *(const float4*)&vs[c * 68 + c0 + 12];
            #pragma unroll
            for (int dd = 0; dd < 16; dd++) {
                o0[dd] = fmaf(p0, vv[dd], o0[dd]);
                o1[dd] = fmaf(p1, vv[dd], o1[dd]);
            }
        }
    }

    int bb = bh >> 4, hh = bh & 15;
    float inv0 = 1.0f / l0s, inv1 = 1.0f / l1s;
    size_t base0 = ((size_t)(bb * N_ + q0 + r0)) * C_ + hh * 64 + c0;
    size_t base1 = ((size_t)(bb * N_ + q0 + r1)) * C_ + hh * 64 + c0;
    #pragma unroll
    for (int dd = 0; dd < 16; dd++) {
        out[base0 + dd] = o0[dd] * inv0;
        out[base1 + dd] = o1[dd] * inv1;
    }
}

// ---------------- launch -----------------------------------------------------
extern "C" void kernel_launch(void* const* d_in, const int* in_sizes, int n_in,
                              void* d_out, int out_size)
{
    const float* x     = (const float*)d_in[0];
    const float* rcos  = (const float*)d_in[1];
    const float* rsin  = (const float*)d_in[2];
    const float* ln1g  = (const float*)d_in[3];
    const float* ln1b  = (const float*)d_in[4];
    const float* Wq    = (const float*)d_in[5];
    const float* bq    = (const float*)d_in[6];
    const float* Wk    = (const float*)d_in[7];
    const float* bk    = (const float*)d_in[8];
    const float* Wv    = (const float*)d_in[9];
    const float* bv    = (const float*)d_in[10];
    const float* Wo    = (const float*)d_in[11];
    const float* bo    = (const float*)d_in[12];
    const float* ln2g  = (const float*)d_in[13];
    const float* ln2b  = (const float*)d_in[14];
    const float* W1    = (const float*)d_in[15];
    const float* b1    = (const float*)d_in[16];
    const float* W2    = (const float*)d_in[17];
    const float* b2    = (const float*)d_in[18];
    float* out = (float*)d_out;

    float *ph, *pq, *pk, *pv, *pao, *px1, *ph2, *pmlp;
    cudaGetSymbolAddress((void**)&ph,   g_h);
    cudaGetSymbolAddress((void**)&pq,   g_q);
    cudaGetSymbolAddress((void**)&pk,   g_k);
    cudaGetSymbolAddress((void**)&pv,   g_v);
    cudaGetSymbolAddress((void**)&pao,  g_ao);
    cudaGetSymbolAddress((void**)&px1,  g_x1);
    cudaGetSymbolAddress((void**)&ph2,  g_h2);
    cudaGetSymbolAddress((void**)&pmlp, g_mlp);

    cudaFuncSetAttribute(attn_kernel,
        cudaFuncAttributeMaxDynamicSharedMemorySize, ATTN_SMEM_BYTES);

    // 1. LN1
    ln_kernel<<<M_, 256>>>(x, ln1g, ln1b, ph);

    // 2. QKV projections (epilogue permutes to (B,H,N,D))
    dim3 gqkv(C_ / 128, M_ / 128);
    mma_gemm<3><<<gqkv, 256>>>(ph, Wq, bq, pq, nullptr, M_, C_, C_);
    mma_gemm<3><<<gqkv, 256>>>(ph, Wk, bk, pk, nullptr, M_, C_, C_);
    mma_gemm<3><<<gqkv, 256>>>(ph, Wv, bv, pv, nullptr, M_, C_, C_);

    // 3. RoPE on q, k
    rope_kernel<<<(B_ * H_ * N_ * 32) / 256, 256>>>(pq, pk, rcos, rsin);

    // 4. Attention
    attn_kernel<<<dim3(N_ / 128, B_ * H_), 256, ATTN_SMEM_BYTES>>>(pq, pk, pv, pao);

    // 5. O projection + residual -> x1
    mma_gemm<1><<<gqkv, 256>>>(pao, Wo, bo, px1, x, M_, C_, C_);

    // 6. LN2
    ln_kernel<<<M_, 256>>>(px1, ln2g, ln2b, ph2);

    // 7. MLP up + GELU
    dim3 gup(F_ / 128, M_ / 128);
    mma_gemm<2><<<gup, 256>>>(ph2, W1, b1, pmlp, nullptr, M_, F_, C_);

    // 8. MLP down + residual -> out
    dim3 gdn(C_ / 128, M_ / 128);
    mma_gemm<1><<<gdn, 256>>>(pmlp, W2, b2, out, px1, M_, C_, F_);
}

// round 4
// speedup vs baseline: 3.7886x; 2.5268x over previous
#include <cuda_runtime.h>
#include <math.h>
#include <stdint.h>

#define B_ 2
#define N_ 2048
#define C_ 1024
#define H_ 16
#define D_ 64
#define F_ 4096
#define M_ (B_*N_)   // 4096 rows

// ---------------- scratch ----------------------------------------------------
__device__ float g_h  [M_*C_];
__device__ float g_q  [M_*C_];   // (B,H,N,D)
__device__ float g_k  [M_*C_];   // (B,H,N,D)
__device__ float g_v  [M_*C_];   // (B,H,N,D)
__device__ float g_ao [M_*C_];   // attention out, (B,N,C)
__device__ float g_x1 [M_*C_];   // residual after attention
__device__ float g_h2 [M_*C_];
__device__ float g_mlp[M_*F_];

// ---------------- helpers ----------------------------------------------------
__device__ __forceinline__ uint32_t f2tf(float f) {
    uint32_t r;
    asm("cvt.rna.tf32.f32 %0, %1;" : "=r"(r) : "f"(f));
    return r;
}

__device__ __forceinline__ void mma_tf32(float* d, const uint32_t* a,
                                         const uint32_t* b) {
    asm volatile(
        "mma.sync.aligned.m16n8k8.row.col.f32.tf32.tf32.f32 "
        "{%0,%1,%2,%3}, {%4,%5,%6,%7}, {%8,%9}, {%0,%1,%2,%3};"
        : "+f"(d[0]), "+f"(d[1]), "+f"(d[2]), "+f"(d[3])
        : "r"(a[0]), "r"(a[1]), "r"(a[2]), "r"(a[3]),
          "r"(b[0]), "r"(b[1]));
}

__device__ __forceinline__ void mma_tf32_b2(float* d, const uint32_t* a,
                                            uint32_t b0, uint32_t b1) {
    asm volatile(
        "mma.sync.aligned.m16n8k8.row.col.f32.tf32.tf32.f32 "
        "{%0,%1,%2,%3}, {%4,%5,%6,%7}, {%8,%9}, {%0,%1,%2,%3};"
        : "+f"(d[0]), "+f"(d[1]), "+f"(d[2]), "+f"(d[3])
        : "r"(a[0]), "r"(a[1]), "r"(a[2]), "r"(a[3]),
          "r"(b0), "r"(b1));
}

// ---------------- LayerNorm --------------------------------------------------
__global__ void ln_kernel(const float* __restrict__ x,
                          const float* __restrict__ g,
                          const float* __restrict__ b,
                          float* __restrict__ out)
{
    int row = blockIdx.x;
    int t = threadIdx.x;
    const float4* xr = (const float4*)(x + (size_t)row * C_);
    float4 xv = xr[t];

    float s  = xv.x + xv.y + xv.z + xv.w;
    float sq = xv.x*xv.x + xv.y*xv.y + xv.z*xv.z + xv.w*xv.w;
    #pragma unroll
    for (int o = 16; o > 0; o >>= 1) {
        s  += __shfl_xor_sync(0xffffffffu, s,  o);
        sq += __shfl_xor_sync(0xffffffffu, sq, o);
    }
    __shared__ float rs[8], rq[8];
    if ((t & 31) == 0) { rs[t >> 5] = s; rq[t >> 5] = sq; }
    __syncthreads();
    __shared__ float s_mean, s_rstd;
    if (t == 0) {
        float ts = 0.f, tq = 0.f;
        #pragma unroll
        for (int i = 0; i < 8; i++) { ts += rs[i]; tq += rq[i]; }
        float mean = ts / (float)C_;
        float var  = tq / (float)C_ - mean * mean;
        s_mean = mean; s_rstd = rsqrtf(var + 1e-6f);
    }
    __syncthreads();
    float mean = s_mean, rstd = s_rstd;
    float4 gv = ((const float4*)g)[t];
    float4 bv = ((const float4*)b)[t];
    float4 ov;
    ov.x = (xv.x - mean) * rstd * gv.x + bv.x;
    ov.y = (xv.y - mean) * rstd * gv.y + bv.y;
    ov.z = (xv.z - mean) * rstd * gv.z + bv.z;
    ov.w = (xv.w - mean) * rstd * gv.w + bv.w;
    ((float4*)(out + (size_t)row * C_))[t] = ov;
}

// ---------------- tf32 mma.sync GEMM (unchanged from R3) ---------------------
#define LDS_ (36)

template<int EPI>
__global__ void __launch_bounds__(256, 1)
mma_gemm(const float* __restrict__ A, const float* __restrict__ Bm,
         const float* __restrict__ bias, float* __restrict__ Cout,
         const float* __restrict__ Res, int M, int N, int K)
{
    __shared__ __align__(16) uint32_t As[128 * LDS_];
    __shared__ __align__(16) uint32_t Bs[128 * LDS_];

    int tid  = threadIdx.x;
    int lane = tid & 31;
    int g    = lane >> 2;
    int q    = lane & 3;
    int wid  = tid >> 5;
    int mbase = (wid & 1) * 64;
    int nbase = (wid >> 1) * 32;
    int m0 = blockIdx.y * 128;
    int n0 = blockIdx.x * 128;

    float acc[4][4][4];
    #pragma unroll
    for (int im = 0; im < 4; im++)
        #pragma unroll
        for (int in_ = 0; in_ < 4; in_++)
            #pragma unroll
            for (int e = 0; e < 4; e++) acc[im][in_][e] = 0.f;

    int lrow[4], lq[4];
    #pragma unroll
    for (int l = 0; l < 4; l++) {
        int idx = tid + l * 256;
        lrow[l] = idx >> 3;
        lq[l]   = idx & 7;
    }

    float4 pa[4], pb[4];
    #pragma unroll
    for (int l = 0; l < 4; l++) {
        pa[l] = *(const float4*)(A + (size_t)(m0 + lrow[l]) * K + lq[l] * 4);
        pb[l] = *(const float4*)(Bm + (size_t)(n0 + lrow[l]) * K + lq[l] * 4);
    }

    const int iters = K >> 5;
    for (int i = 0; i < iters; i++) {
        __syncthreads();
        #pragma unroll
        for (int l = 0; l < 4; l++) {
            uint4 va = make_uint4(f2tf(pa[l].x), f2tf(pa[l].y),
                                  f2tf(pa[l].z), f2tf(pa[l].w));
            *(uint4*)&As[lrow[l] * LDS_ + lq[l] * 4] = va;
            uint4 vb = make_uint4(f2tf(pb[l].x), f2tf(pb[l].y),
                                  f2tf(pb[l].z), f2tf(pb[l].w));
            *(uint4*)&Bs[lrow[l] * LDS_ + lq[l] * 4] = vb;
        }
        __syncthreads();

        if (i + 1 < iters) {
            int k0 = (i + 1) << 5;
            #pragma unroll
            for (int l = 0; l < 4; l++) {
                pa[l] = *(const float4*)(A + (size_t)(m0 + lrow[l]) * K + k0 + lq[l] * 4);
                pb[l] = *(const float4*)(Bm + (size_t)(n0 + lrow[l]) * K + k0 + lq[l] * 4);
            }
        }

        #pragma unroll
        for (int ks = 0; ks < 4; ks++) {
            uint32_t af[4][4], bf[4][2];
            int kc = ks * 8 + q;
            #pragma unroll
            for (int im = 0; im < 4; im++) {
                int r = (mbase + im * 16 + g) * LDS_;
                af[im][0] = As[r + kc];
                af[im][1] = As[r + 8 * LDS_ + kc];
                af[im][2] = As[r + kc + 4];
                af[im][3] = As[r + 8 * LDS_ + kc + 4];
            }
            #pragma unroll
            for (int in_ = 0; in_ < 4; in_++) {
                int r = (nbase + in_ * 8 + g) * LDS_;
                bf[in_][0] = Bs[r + kc];
                bf[in_][1] = Bs[r + kc + 4];
            }
            #pragma unroll
            for (int im = 0; im < 4; im++)
                #pragma unroll
                for (int in_ = 0; in_ < 4; in_++)
                    mma_tf32(acc[im][in_], af[im], bf[in_]);
        }
    }

    #pragma unroll
    for (int im = 0; im < 4; im++) {
        int mrow0 = m0 + mbase + im * 16 + g;
        #pragma unroll
        for (int in_ = 0; in_ < 4; in_++) {
            int n = n0 + nbase + in_ * 8 + 2 * q;
            float b0 = bias[n], b1 = bias[n + 1];
            #pragma unroll
            for (int half = 0; half < 2; half++) {
                int m = mrow0 + half * 8;
                float v0 = acc[im][in_][half * 2 + 0] + b0;
                float v1 = acc[im][in_][half * 2 + 1] + b1;
                if (EPI == 1) {
                    float2 rr = *(const float2*)(Res + (size_t)m * N + n);
                    v0 += rr.x; v1 += rr.y;
                } else if (EPI == 2) {
                    v0 = 0.5f * v0 * (1.0f + erff(v0 * 0.70710678118654752f));
                    v1 = 0.5f * v1 * (1.0f + erff(v1 * 0.70710678118654752f));
                }
                float2 ov = make_float2(v0, v1);
                if (EPI == 3) {
                    int bb  = m >> 11;
                    int pos = m & (N_ - 1);
                    int hh  = n >> 6;
                    int dd  = n & (D_ - 1);
                    *(float2*)(Cout + (((size_t)(bb * H_ + hh)) * N_ + pos) * D_ + dd) = ov;
                } else {
                    *(float2*)(Cout + (size_t)m * N + n) = ov;
                }
            }
        }
    }
}

// ---------------- RoPE -------------------------------------------------------
__global__ void rope_kernel(float* __restrict__ q, float* __restrict__ k,
                            const float* __restrict__ cosb,
                            const float* __restrict__ sinb)
{
    int idx = blockIdx.x * blockDim.x + threadIdx.x;
    int d  = idx & 31;
    int n  = (idx >> 5) & (N_ - 1);
    int bh = idx >> 16;

    float c1 = cosb[n * D_ + d],      s1 = sinb[n * D_ + d];
    float c2 = cosb[n * D_ + d + 32], s2 = sinb[n * D_ + d + 32];
    size_t base = ((size_t)bh * N_ + n) * D_;

    float q1 = q[base + d], q2 = q[base + d + 32];
    q[base + d]      = q1 * c1 - q2 * s1;
    q[base + d + 32] = q2 * c2 + q1 * s2;

    float k1 = k[base + d], k2 = k[base + d + 32];
    k[base + d]      = k1 * c1 - k2 * s1;
    k[base + d + 32] = k2 * c2 + k1 * s2;
}

// ---------------- Flash attention via tf32 mma.sync --------------------------
// CTA: 128 q rows, 8 warps, warp w owns rows 16w..16w+15. 64-key tiles.
// smem (uint32): Ks[64*68] | Vs[64*68] | Ps[128*68]
#define AT_LDS 68
#define AKS_OFF 0
#define AVS_OFF (64*AT_LDS)
#define APS_OFF (2*64*AT_LDS)
#define ATTN_SMEM_WORDS (APS_OFF + 128*AT_LDS)
#define ATTN_SMEM_BYTES (ATTN_SMEM_WORDS * 4)

__global__ void __launch_bounds__(256, 2)
attn_mma(const float* __restrict__ q, const float* __restrict__ k,
         const float* __restrict__ v, float* __restrict__ out)
{
    extern __shared__ uint32_t asm_[];
    uint32_t* Ks = asm_ + AKS_OFF;
    uint32_t* Vs = asm_ + AVS_OFF;
    uint32_t* Ps = asm_ + APS_OFF;

    int bh = blockIdx.y;
    int q0 = blockIdx.x * 128;
    const float* qb = q + (size_t)bh * N_ * D_;
    const float* kb = k + (size_t)bh * N_ * D_;
    const float* vb = v + (size_t)bh * N_ * D_;

    int tid  = threadIdx.x;
    int lane = tid & 31;
    int g    = lane >> 2;       // 0..7
    int qq   = lane & 3;        // 0..3
    int wid  = tid >> 5;        // 0..7
    int row0 = wid * 16 + g;    // warp-local S row (and row0+8)

    const float scale = 0.125f;  // D^-0.5

    // ---- stage Q (scaled) through Ps, then pick up A-fragments into regs ----
    for (int i = tid; i < 128 * 64; i += 256) {
        int r = i >> 6, d = i & 63;
        Ps[r * AT_LDS + d] = __float_as_uint(qb[(size_t)(q0 + r) * D_ + d] * scale);
    }
    __syncthreads();
    uint32_t qa[8][4];
    #pragma unroll
    for (int ks = 0; ks < 8; ks++) {
        int kc = ks * 8 + qq;
        qa[ks][0] = f2tf(__uint_as_float(Ps[row0 * AT_LDS + kc]));
        qa[ks][1] = f2tf(__uint_as_float(Ps[(row0 + 8) * AT_LDS + kc]));
        qa[ks][2] = f2tf(__uint_as_float(Ps[row0 * AT_LDS + kc + 4]));
        qa[ks][3] = f2tf(__uint_as_float(Ps[(row0 + 8) * AT_LDS + kc + 4]));
    }

    float oacc[8][4];
    #pragma unroll
    for (int nt = 0; nt < 8; nt++)
        #pragma unroll
        for (int e = 0; e < 4; e++) oacc[nt][e] = 0.f;
    float m0 = -1e30f, m1 = -1e30f, l0 = 0.f, l1 = 0.f;

    for (int kt = 0; kt < N_; kt += 64) {
        __syncthreads();   // prior-tile reads of Ks/Vs done; Q staging done
        #pragma unroll
        for (int l = 0; l < 4; l++) {
            int idx = tid + l * 256;         // 0..1023
            int r  = idx >> 4;               // 0..63
            int c4 = (idx & 15) * 4;
            float4 kv = *(const float4*)(kb + (size_t)(kt + r) * D_ + c4);
            *(uint4*)&Ks[r * AT_LDS + c4] =
                make_uint4(f2tf(kv.x), f2tf(kv.y), f2tf(kv.z), f2tf(kv.w));
            float4 vv = *(const float4*)(vb + (size_t)(kt + r) * D_ + c4);
            *(uint4*)&Vs[r * AT_LDS + c4] =
                make_uint4(f2tf(vv.x), f2tf(vv.y), f2tf(vv.z), f2tf(vv.w));
        }
        __syncthreads();

        // ---- S = Q @ K^T : warp tile 16 x 64 ----
        float sacc[8][4];
        #pragma unroll
        for (int nt = 0; nt < 8; nt++)
            #pragma unroll
            for (int e = 0; e < 4; e++) sacc[nt][e] = 0.f;

        #pragma unroll
        for (int ks = 0; ks < 8; ks++) {
            int kc = ks * 8 + qq;
            #pragma unroll
            for (int nt = 0; nt < 8; nt++) {
                int r = (nt * 8 + g) * AT_LDS;
                mma_tf32_b2(sacc[nt], qa[ks], Ks[r + kc], Ks[r + kc + 4]);
            }
        }

        // ---- online softmax (warp-local; rows row0 and row0+8) ----
        float mt0 = -1e30f, mt1 = -1e30f;
        #pragma unroll
        for (int nt = 0; nt < 8; nt++) {
            mt0 = fmaxf(mt0, fmaxf(sacc[nt][0], sacc[nt][1]));
            mt1 = fmaxf(mt1, fmaxf(sacc[nt][2], sacc[nt][3]));
        }
        mt0 = fmaxf(mt0, __shfl_xor_sync(0xffffffffu, mt0, 1));
        mt0 = fmaxf(mt0, __shfl_xor_sync(0xffffffffu, mt0, 2));
        mt1 = fmaxf(mt1, __shfl_xor_sync(0xffffffffu, mt1, 1));
        mt1 = fmaxf(mt1, __shfl_xor_sync(0xffffffffu, mt1, 2));

        float mn0 = fmaxf(m0, mt0), mn1 = fmaxf(m1, mt1);
        float cr0 = __expf(m0 - mn0), cr1 = __expf(m1 - mn1);
        float ls0 = 0.f, ls1 = 0.f;
        #pragma unroll
        for (int nt = 0; nt < 8; nt++) {
            float p00 = __expf(sacc[nt][0] - mn0);
            float p01 = __expf(sacc[nt][1] - mn0);
            float p10 = __expf(sacc[nt][2] - mn1);
            float p11 = __expf(sacc[nt][3] - mn1);
            ls0 += p00 + p01;
            ls1 += p10 + p11;
            int c = nt * 8 + 2 * qq;
            *(uint2*)&Ps[row0 * AT_LDS + c]       = make_uint2(f2tf(p00), f2tf(p01));
            *(uint2*)&Ps[(row0 + 8) * AT_LDS + c] = make_uint2(f2tf(p10), f2tf(p11));
        }
        ls0 += __shfl_xor_sync(0xffffffffu, ls0, 1);
        ls0 += __shfl_xor_sync(0xffffffffu, ls0, 2);
        ls1 += __shfl_xor_sync(0xffffffffu, ls1, 1);
        ls1 += __shfl_xor_sync(0xffffffffu, ls1, 2);
        l0 = l0 * cr0 + ls0;  m0 = mn0;
        l1 = l1 * cr1 + ls1;  m1 = mn1;
        #pragma unroll
        for (int nt = 0; nt < 8; nt++) {
            oacc[nt][0] *= cr0; oacc[nt][1] *= cr0;
            oacc[nt][2] *= cr1; oacc[nt][3] *= cr1;
        }
        __syncwarp();   // P band is warp-private

        // ---- O += P @ V : warp tile 16 x 64, K = 64 keys ----
        #pragma unroll
        for (int ks = 0; ks < 8; ks++) {
            int kc = ks * 8 + qq;
            uint32_t pa[4];
            pa[0] = Ps[row0 * AT_LDS + kc];
            pa[1] = Ps[(row0 + 8) * AT_LDS + kc];
            pa[2] = Ps[row0 * AT_LDS + kc + 4];
            pa[3] = Ps[(row0 + 8) * AT_LDS + kc + 4];
            #pragma unroll
            for (int nt = 0; nt < 8; nt++) {
                int c = nt * 8 + g;
                mma_tf32_b2(oacc[nt], pa,
                            Vs[(ks * 8 + qq) * AT_LDS + c],
                            Vs[(ks * 8 + qq + 4) * AT_LDS + c]);
            }
        }
        __syncwarp();   // P reads done before next tile's writes
    }

    // ---- write out to (B, N, H*D) ----
    int bb = bh >> 4, hh = bh & 15;
    float inv0 = 1.0f / l0, inv1 = 1.0f / l1;
    size_t base0 = ((size_t)(bb * N_ + q0 + row0)) * C_ + hh * 64;
    size_t base1 = ((size_t)(bb * N_ + q0 + row0 + 8)) * C_ + hh * 64;
    #pragma unroll
    for (int nt = 0; nt < 8; nt++) {
        int c = nt * 8 + 2 * qq;
        *(float2*)(out + base0 + c) = make_float2(oacc[nt][0] * inv0, oacc[nt][1] * inv0);
        *(float2*)(out + base1 + c) = make_float2(oacc[nt][2] * inv1, oacc[nt][3] * inv1);
    }
}

// ---------------- launch -----------------------------------------------------
extern "C" void kernel_launch(void* const* d_in, const int* in_sizes, int n_in,
                              void* d_out, int out_size)
{
    const float* x     = (const float*)d_in[0];
    const float* rcos  = (const float*)d_in[1];
    const float* rsin  = (const float*)d_in[2];
    const float* ln1g  = (const float*)d_in[3];
    const float* ln1b  = (const float*)d_in[4];
    const float* Wq    = (const float*)d_in[5];
    const float* bq    = (const float*)d_in[6];
    const float* Wk    = (const float*)d_in[7];
    const float* bk    = (const float*)d_in[8];
    const float* Wv    = (const float*)d_in[9];
    const float* bv    = (const float*)d_in[10];
    const float* Wo    = (const float*)d_in[11];
    const float* bo    = (const float*)d_in[12];
    const float* ln2g  = (const float*)d_in[13];
    const float* ln2b  = (const float*)d_in[14];
    const float* W1    = (const float*)d_in[15];
    const float* b1    = (const float*)d_in[16];
    const float* W2    = (const float*)d_in[17];
    const float* b2    = (const float*)d_in[18];
    float* out = (float*)d_out;

    float *ph, *pq, *pk, *pv, *pao, *px1, *ph2, *pmlp;
    cudaGetSymbolAddress((void**)&ph,   g_h);
    cudaGetSymbolAddress((void**)&pq,   g_q);
    cudaGetSymbolAddress((void**)&pk,   g_k);
    cudaGetSymbolAddress((void**)&pv,   g_v);
    cudaGetSymbolAddress((void**)&pao,  g_ao);
    cudaGetSymbolAddress((void**)&px1,  g_x1);
    cudaGetSymbolAddress((void**)&ph2,  g_h2);
    cudaGetSymbolAddress((void**)&pmlp, g_mlp);

    cudaFuncSetAttribute(attn_mma,
        cudaFuncAttributeMaxDynamicSharedMemorySize, ATTN_SMEM_BYTES);

    // 1. LN1
    ln_kernel<<<M_, 256>>>(x, ln1g, ln1b, ph);

    // 2. QKV projections (epilogue permutes to (B,H,N,D))
    dim3 gqkv(C_ / 128, M_ / 128);
    mma_gemm<3><<<gqkv, 256>>>(ph, Wq, bq, pq, nullptr, M_, C_, C_);
    mma_gemm<3><<<gqkv, 256>>>(ph, Wk, bk, pk, nullptr, M_, C_, C_);
    mma_gemm<3><<<gqkv, 256>>>(ph, Wv, bv, pv, nullptr, M_, C_, C_);

    // 3. RoPE on q, k
    rope_kernel<<<(B_ * H_ * N_ * 32) / 256, 256>>>(pq, pk, rcos, rsin);

    // 4. Attention (tf32 mma)
    attn_mma<<<dim3(N_ / 128, B_ * H_), 256, ATTN_SMEM_BYTES>>>(pq, pk, pv, pao);

    // 5. O projection + residual -> x1
    mma_gemm<1><<<gqkv, 256>>>(pao, Wo, bo, px1, x, M_, C_, C_);

    // 6. LN2
    ln_kernel<<<M_, 256>>>(px1, ln2g, ln2b, ph2);

    // 7. MLP up + GELU
    dim3 gup(F_ / 128, M_ / 128);
    mma_gemm<2><<<gup, 256>>>(ph2, W1, b1, pmlp, nullptr, M_, F_, C_);

    // 8. MLP down + residual -> out
    dim3 gdn(C_ / 128, M_ / 128);
    mma_gemm<1><<<gdn, 256>>>(pmlp, W2, b2, out, px1, M_, C_, F_);
}

// round 5
// speedup vs baseline: 4.0053x; 1.0572x over previous
#include <cuda_runtime.h>
#include <math.h>
#include <stdint.h>

#define B_ 2
#define N_ 2048
#define C_ 1024
#define H_ 16
#define D_ 64
#define F_ 4096
#define M_ (B_*N_)   // 4096 rows

// ---------------- scratch ----------------------------------------------------
__device__ float g_h  [M_*C_];
__device__ float g_q  [M_*C_];   // (B,H,N,D)
__device__ float g_k  [M_*C_];   // (B,H,N,D)
__device__ float g_v  [M_*C_];   // (B,H,N,D)
__device__ float g_ao [M_*C_];   // attention out, (B,N,C)
__device__ float g_x1 [M_*C_];   // residual after attention
__device__ float g_h2 [M_*C_];
__device__ float g_mlp[M_*F_];

// ---------------- helpers ----------------------------------------------------
__device__ __forceinline__ uint32_t f2tf(float f) {
    uint32_t r;
    asm("cvt.rna.tf32.f32 %0, %1;" : "=r"(r) : "f"(f));
    return r;
}

__device__ __forceinline__ uint32_t smem_u32(const void* p) {
    uint32_t a;
    asm("{ .reg .u64 t; cvta.to.shared.u64 t, %1; cvt.u32.u64 %0, t; }"
        : "=r"(a) : "l"(p));
    return a;
}

__device__ __forceinline__ void cp_async16(uint32_t s, const float* g) {
    asm volatile("cp.async.cg.shared.global [%0], [%1], 16;"
                 :: "r"(s), "l"(__cvta_generic_to_global(g)) : "memory");
}

__device__ __forceinline__ void cp_commit() {
    asm volatile("cp.async.commit_group;" ::: "memory");
}

__device__ __forceinline__ void mma_tf32(float* d, const uint32_t* a,
                                         const uint32_t* b) {
    asm volatile(
        "mma.sync.aligned.m16n8k8.row.col.f32.tf32.tf32.f32 "
        "{%0,%1,%2,%3}, {%4,%5,%6,%7}, {%8,%9}, {%0,%1,%2,%3};"
        : "+f"(d[0]), "+f"(d[1]), "+f"(d[2]), "+f"(d[3])
        : "r"(a[0]), "r"(a[1]), "r"(a[2]), "r"(a[3]),
          "r"(b[0]), "r"(b[1]));
}

__device__ __forceinline__ void mma_tf32_b2(float* d, const uint32_t* a,
                                            uint32_t b0, uint32_t b1) {
    asm volatile(
        "mma.sync.aligned.m16n8k8.row.col.f32.tf32.tf32.f32 "
        "{%0,%1,%2,%3}, {%4,%5,%6,%7}, {%8,%9}, {%0,%1,%2,%3};"
        : "+f"(d[0]), "+f"(d[1]), "+f"(d[2]), "+f"(d[3])
        : "r"(a[0]), "r"(a[1]), "r"(a[2]), "r"(a[3]),
          "r"(b0), "r"(b1));
}

// ---------------- LayerNorm --------------------------------------------------
__global__ void ln_kernel(const float* __restrict__ x,
                          const float* __restrict__ g,
                          const float* __restrict__ b,
                          float* __restrict__ out)
{
    int row = blockIdx.x;
    int t = threadIdx.x;
    const float4* xr = (const float4*)(x + (size_t)row * C_);
    float4 xv = xr[t];

    float s  = xv.x + xv.y + xv.z + xv.w;
    float sq = xv.x*xv.x + xv.y*xv.y + xv.z*xv.z + xv.w*xv.w;
    #pragma unroll
    for (int o = 16; o > 0; o >>= 1) {
        s  += __shfl_xor_sync(0xffffffffu, s,  o);
        sq += __shfl_xor_sync(0xffffffffu, sq, o);
    }
    __shared__ float rs[8], rq[8];
    if ((t & 31) == 0) { rs[t >> 5] = s; rq[t >> 5] = sq; }
    __syncthreads();
    __shared__ float s_mean, s_rstd;
    if (t == 0) {
        float ts = 0.f, tq = 0.f;
        #pragma unroll
        for (int i = 0; i < 8; i++) { ts += rs[i]; tq += rq[i]; }
        float mean = ts / (float)C_;
        float var  = tq / (float)C_ - mean * mean;
        s_mean = mean; s_rstd = rsqrtf(var + 1e-6f);
    }
    __syncthreads();
    float mean = s_mean, rstd = s_rstd;
    float4 gv = ((const float4*)g)[t];
    float4 bv = ((const float4*)b)[t];
    float4 ov;
    ov.x = (xv.x - mean) * rstd * gv.x + bv.x;
    ov.y = (xv.y - mean) * rstd * gv.y + bv.y;
    ov.z = (xv.z - mean) * rstd * gv.z + bv.z;
    ov.w = (xv.w - mean) * rstd * gv.w + bv.w;
    ((float4*)(out + (size_t)row * C_))[t] = ov;
}

// ---------------- tf32 mma.sync GEMM, cp.async 4-stage pipeline --------------
// C[M,N] = A[M,K] @ B[N,K]^T; raw fp32 bits fed to HMMA (hw tf32 truncation).
// EPI: 0 = bias, 1 = bias + residual, 2 = bias + exact GELU,
//      3 = bias + permuted store to (B,H,N,D)
#define LDS_ 36
#define STAGES 4
#define A_BYTES_ (128 * LDS_ * 4)          // 18432
#define STAGE_BYTES_ (2 * A_BYTES_)        // 36864
#define GEMM_SMEM (STAGES * STAGE_BYTES_)  // 147456

struct GOp { const float* B; const float* bias; float* C; };

template<int EPI>
__global__ void __launch_bounds__(256, 1)
mma_gemm(const float* __restrict__ A, GOp o0, GOp o1, GOp o2,
         const float* __restrict__ Res, int M, int N, int K)
{
    extern __shared__ char dsm[];
    const GOp op = (blockIdx.z == 0) ? o0 : ((blockIdx.z == 1) ? o1 : o2);

    int tid  = threadIdx.x;
    int lane = tid & 31;
    int g    = lane >> 2;
    int q    = lane & 3;
    int wid  = tid >> 5;
    int mbase = (wid & 1) * 64;
    int nbase = (wid >> 1) * 32;
    int m0 = blockIdx.y * 128;
    int n0 = blockIdx.x * 128;

    uint32_t sbase = smem_u32(dsm);

    // per-thread cp.async slots: 4 chunks of A + 4 of B per stage
    const float* aptr[4];
    const float* bptr[4];
    uint32_t soff[4];
    #pragma unroll
    for (int l = 0; l < 4; l++) {
        int idx = tid + l * 256;       // 0..1023
        int row = idx >> 3;            // 0..127
        int qf  = idx & 7;             // float4 slot in 32-float row
        aptr[l] = A + (size_t)(m0 + row) * K + qf * 4;
        bptr[l] = op.B + (size_t)(n0 + row) * K + qf * 4;
        soff[l] = (uint32_t)(row * LDS_ + qf * 4) * 4;
    }

    float acc[4][4][4];
    #pragma unroll
    for (int im = 0; im < 4; im++)
        #pragma unroll
        for (int in_ = 0; in_ < 4; in_++)
            #pragma unroll
            for (int e = 0; e < 4; e++) acc[im][in_][e] = 0.f;

    const int iters = K >> 5;

    // prologue: stages 0..STAGES-2
    #pragma unroll
    for (int s = 0; s < STAGES - 1; s++) {
        uint32_t sa = sbase + s * STAGE_BYTES_;
        uint32_t sbm = sa + A_BYTES_;
        int k0 = s << 5;
        #pragma unroll
        for (int l = 0; l < 4; l++) {
            cp_async16(sa + soff[l],  aptr[l] + k0);
            cp_async16(sbm + soff[l], bptr[l] + k0);
        }
        cp_commit();
    }

    for (int i = 0; i < iters; i++) {
        asm volatile("cp.async.wait_group %0;" :: "n"(STAGES - 2) : "memory");
        __syncthreads();

        // issue load for stage i+STAGES-1
        int nxt = i + STAGES - 1;
        if (nxt < iters) {
            int st = nxt & (STAGES - 1);
            uint32_t sa = sbase + st * STAGE_BYTES_;
            uint32_t sbm = sa + A_BYTES_;
            int k0 = nxt << 5;
            #pragma unroll
            for (int l = 0; l < 4; l++) {
                cp_async16(sa + soff[l],  aptr[l] + k0);
                cp_async16(sbm + soff[l], bptr[l] + k0);
            }
        }
        cp_commit();

        // compute on stage i
        const uint32_t* As = (const uint32_t*)(dsm + (i & (STAGES - 1)) * STAGE_BYTES_);
        const uint32_t* Bs = As + 128 * LDS_;

        #pragma unroll
        for (int ks = 0; ks < 4; ks++) {
            uint32_t af[4][4], bf[4][2];
            int kc = ks * 8 + q;
            #pragma unroll
            for (int im = 0; im < 4; im++) {
                int r = (mbase + im * 16 + g) * LDS_;
                af[im][0] = As[r + kc];
                af[im][1] = As[r + 8 * LDS_ + kc];
                af[im][2] = As[r + kc + 4];
                af[im][3] = As[r + 8 * LDS_ + kc + 4];
            }
            #pragma unroll
            for (int in_ = 0; in_ < 4; in_++) {
                int r = (nbase + in_ * 8 + g) * LDS_;
                bf[in_][0] = Bs[r + kc];
                bf[in_][1] = Bs[r + kc + 4];
            }
            #pragma unroll
            for (int im = 0; im < 4; im++)
                #pragma unroll
                for (int in_ = 0; in_ < 4; in_++)
                    mma_tf32(acc[im][in_], af[im], bf[in_]);
        }
    }

    // ---------------- epilogue ----------------
    #pragma unroll
    for (int im = 0; im < 4; im++) {
        int mrow0 = m0 + mbase + im * 16 + g;
        #pragma unroll
        for (int in_ = 0; in_ < 4; in_++) {
            int n = n0 + nbase + in_ * 8 + 2 * q;
            float b0 = op.bias[n], b1 = op.bias[n + 1];
            #pragma unroll
            for (int half = 0; half < 2; half++) {
                int m = mrow0 + half * 8;
                float v0 = acc[im][in_][half * 2 + 0] + b0;
                float v1 = acc[im][in_][half * 2 + 1] + b1;
                if (EPI == 1) {
                    float2 rr = *(const float2*)(Res + (size_t)m * N + n);
                    v0 += rr.x; v1 += rr.y;
                } else if (EPI == 2) {
                    v0 = 0.5f * v0 * (1.0f + erff(v0 * 0.70710678118654752f));
                    v1 = 0.5f * v1 * (1.0f + erff(v1 * 0.70710678118654752f));
                }
                float2 ov = make_float2(v0, v1);
                if (EPI == 3) {
                    int bb  = m >> 11;
                    int pos = m & (N_ - 1);
                    int hh  = n >> 6;
                    int dd  = n & (D_ - 1);
                    *(float2*)(op.C + (((size_t)(bb * H_ + hh)) * N_ + pos) * D_ + dd) = ov;
                } else {
                    *(float2*)(op.C + (size_t)m * N + n) = ov;
                }
            }
        }
    }
}

// ---------------- RoPE -------------------------------------------------------
__global__ void rope_kernel(float* __restrict__ q, float* __restrict__ k,
                            const float* __restrict__ cosb,
                            const float* __restrict__ sinb)
{
    int idx = blockIdx.x * blockDim.x + threadIdx.x;
    int d  = idx & 31;
    int n  = (idx >> 5) & (N_ - 1);
    int bh = idx >> 16;

    float c1 = cosb[n * D_ + d],      s1 = sinb[n * D_ + d];
    float c2 = cosb[n * D_ + d + 32], s2 = sinb[n * D_ + d + 32];
    size_t base = ((size_t)bh * N_ + n) * D_;

    float q1 = q[base + d], q2 = q[base + d + 32];
    q[base + d]      = q1 * c1 - q2 * s1;
    q[base + d + 32] = q2 * c2 + q1 * s2;

    float k1 = k[base + d], k2 = k[base + d + 32];
    k[base + d]      = k1 * c1 - k2 * s1;
    k[base + d + 32] = k2 * c2 + k1 * s2;
}

// ---------------- Flash attention via tf32 mma.sync --------------------------
#define AT_LDS 68
#define AKS_OFF 0
#define AVS_OFF (64*AT_LDS)
#define APS_OFF (2*64*AT_LDS)
#define ATTN_SMEM_WORDS (APS_OFF + 128*AT_LDS)
#define ATTN_SMEM_BYTES (ATTN_SMEM_WORDS * 4)

__global__ void __launch_bounds__(256, 2)
attn_mma(const float* __restrict__ q, const float* __restrict__ k,
         const float* __restrict__ v, float* __restrict__ out)
{
    extern __shared__ uint32_t asm_[];
    uint32_t* Ks = asm_ + AKS_OFF;
    uint32_t* Vs = asm_ + AVS_OFF;
    uint32_t* Ps = asm_ + APS_OFF;

    int bh = blockIdx.y;
    int q0 = blockIdx.x * 128;
    const float* qb = q + (size_t)bh * N_ * D_;
    const float* kb = k + (size_t)bh * N_ * D_;
    const float* vb = v + (size_t)bh * N_ * D_;

    int tid  = threadIdx.x;
    int lane = tid & 31;
    int g    = lane >> 2;
    int qq   = lane & 3;
    int wid  = tid >> 5;
    int row0 = wid * 16 + g;

    const float scale = 0.125f;

    for (int i = tid; i < 128 * 64; i += 256) {
        int r = i >> 6, d = i & 63;
        Ps[r * AT_LDS + d] = __float_as_uint(qb[(size_t)(q0 + r) * D_ + d] * scale);
    }
    __syncthreads();
    uint32_t qa[8][4];
    #pragma unroll
    for (int ks = 0; ks < 8; ks++) {
        int kc = ks * 8 + qq;
        qa[ks][0] = f2tf(__uint_as_float(Ps[row0 * AT_LDS + kc]));
        qa[ks][1] = f2tf(__uint_as_float(Ps[(row0 + 8) * AT_LDS + kc]));
        qa[ks][2] = f2tf(__uint_as_float(Ps[row0 * AT_LDS + kc + 4]));
        qa[ks][3] = f2tf(__uint_as_float(Ps[(row0 + 8) * AT_LDS + kc + 4]));
    }

    float oacc[8][4];
    #pragma unroll
    for (int nt = 0; nt < 8; nt++)
        #pragma unroll
        for (int e = 0; e < 4; e++) oacc[nt][e] = 0.f;
    float m0 = -1e30f, m1 = -1e30f, l0 = 0.f, l1 = 0.f;

    for (int kt = 0; kt < N_; kt += 64) {
        __syncthreads();
        #pragma unroll
        for (int l = 0; l < 4; l++) {
            int idx = tid + l * 256;
            int r  = idx >> 4;
            int c4 = (idx & 15) * 4;
            float4 kv = *(const float4*)(kb + (size_t)(kt + r) * D_ + c4);
            *(uint4*)&Ks[r * AT_LDS + c4] =
                make_uint4(f2tf(kv.x), f2tf(kv.y), f2tf(kv.z), f2tf(kv.w));
            float4 vv = *(const float4*)(vb + (size_t)(kt + r) * D_ + c4);
            *(uint4*)&Vs[r * AT_LDS + c4] =
                make_uint4(f2tf(vv.x), f2tf(vv.y), f2tf(vv.z), f2tf(vv.w));
        }
        __syncthreads();

        float sacc[8][4];
        #pragma unroll
        for (int nt = 0; nt < 8; nt++)
            #pragma unroll
            for (int e = 0; e < 4; e++) sacc[nt][e] = 0.f;

        #pragma unroll
        for (int ks = 0; ks < 8; ks++) {
            int kc = ks * 8 + qq;
            #pragma unroll
            for (int nt = 0; nt < 8; nt++) {
                int r = (nt * 8 + g) * AT_LDS;
                mma_tf32_b2(sacc[nt], qa[ks], Ks[r + kc], Ks[r + kc + 4]);
            }
        }

        float mt0 = -1e30f, mt1 = -1e30f;
        #pragma unroll
        for (int nt = 0; nt < 8; nt++) {
            mt0 = fmaxf(mt0, fmaxf(sacc[nt][0], sacc[nt][1]));
            mt1 = fmaxf(mt1, fmaxf(sacc[nt][2], sacc[nt][3]));
        }
        mt0 = fmaxf(mt0, __shfl_xor_sync(0xffffffffu, mt0, 1));
        mt0 = fmaxf(mt0, __shfl_xor_sync(0xffffffffu, mt0, 2));
        mt1 = fmaxf(mt1, __shfl_xor_sync(0xffffffffu, mt1, 1));
        mt1 = fmaxf(mt1, __shfl_xor_sync(0xffffffffu, mt1, 2));

        float mn0 = fmaxf(m0, mt0), mn1 = fmaxf(m1, mt1);
        float cr0 = __expf(m0 - mn0), cr1 = __expf(m1 - mn1);
        float ls0 = 0.f, ls1 = 0.f;
        #pragma unroll
        for (int nt = 0; nt < 8; nt++) {
            float p00 = __expf(sacc[nt][0] - mn0);
            float p01 = __expf(sacc[nt][1] - mn0);
            float p10 = __expf(sacc[nt][2] - mn1);
            float p11 = __expf(sacc[nt][3] - mn1);
            ls0 += p00 + p01;
            ls1 += p10 + p11;
            int c = nt * 8 + 2 * qq;
            *(uint2*)&Ps[row0 * AT_LDS + c]       = make_uint2(f2tf(p00), f2tf(p01));
            *(uint2*)&Ps[(row0 + 8) * AT_LDS + c] = make_uint2(f2tf(p10), f2tf(p11));
        }
        ls0 += __shfl_xor_sync(0xffffffffu, ls0, 1);
        ls0 += __shfl_xor_sync(0xffffffffu, ls0, 2);
        ls1 += __shfl_xor_sync(0xffffffffu, ls1, 1);
        ls1 += __shfl_xor_sync(0xffffffffu, ls1, 2);
        l0 = l0 * cr0 + ls0;  m0 = mn0;
        l1 = l1 * cr1 + ls1;  m1 = mn1;
        #pragma unroll
        for (int nt = 0; nt < 8; nt++) {
            oacc[nt][0] *= cr0; oacc[nt][1] *= cr0;
            oacc[nt][2] *= cr1; oacc[nt][3] *= cr1;
        }
        __syncwarp();

        #pragma unroll
        for (int ks = 0; ks < 8; ks++) {
            int kc = ks * 8 + qq;
            uint32_t pa[4];
            pa[0] = Ps[row0 * AT_LDS + kc];
            pa[1] = Ps[(row0 + 8) * AT_LDS + kc];
            pa[2] = Ps[row0 * AT_LDS + kc + 4];
            pa[3] = Ps[(row0 + 8) * AT_LDS + kc + 4];
            #pragma unroll
            for (int nt = 0; nt < 8; nt++) {
                int c = nt * 8 + g;
                mma_tf32_b2(oacc[nt], pa,
                            Vs[(ks * 8 + qq) * AT_LDS + c],
                            Vs[(ks * 8 + qq + 4) * AT_LDS + c]);
            }
        }
        __syncwarp();
    }

    int bb = bh >> 4, hh = bh & 15;
    float inv0 = 1.0f / l0, inv1 = 1.0f / l1;
    size_t base0 = ((size_t)(bb * N_ + q0 + row0)) * C_ + hh * 64;
    size_t base1 = ((size_t)(bb * N_ + q0 + row0 + 8)) * C_ + hh * 64;
    #pragma unroll
    for (int nt = 0; nt < 8; nt++) {
        int c = nt * 8 + 2 * qq;
        *(float2*)(out + base0 + c) = make_float2(oacc[nt][0] * inv0, oacc[nt][1] * inv0);
        *(float2*)(out + base1 + c) = make_float2(oacc[nt][2] * inv1, oacc[nt][3] * inv1);
    }
}

// ---------------- launch -----------------------------------------------------
extern "C" void kernel_launch(void* const* d_in, const int* in_sizes, int n_in,
                              void* d_out, int out_size)
{
    const float* x     = (const float*)d_in[0];
    const float* rcos  = (const float*)d_in[1];
    const float* rsin  = (const float*)d_in[2];
    const float* ln1g  = (const float*)d_in[3];
    const float* ln1b  = (const float*)d_in[4];
    const float* Wq    = (const float*)d_in[5];
    const float* bq    = (const float*)d_in[6];
    const float* Wk    = (const float*)d_in[7];
    const float* bk    = (const float*)d_in[8];
    const float* Wv    = (const float*)d_in[9];
    const float* bv    = (const float*)d_in[10];
    const float* Wo    = (const float*)d_in[11];
    const float* bo    = (const float*)d_in[12];
    const float* ln2g  = (const float*)d_in[13];
    const float* ln2b  = (const float*)d_in[14];
    const float* W1    = (const float*)d_in[15];
    const float* b1    = (const float*)d_in[16];
    const float* W2    = (const float*)d_in[17];
    const float* b2    = (const float*)d_in[18];
    float* out = (float*)d_out;

    float *ph, *pq, *pk, *pv, *pao, *px1, *ph2, *pmlp;
    cudaGetSymbolAddress((void**)&ph,   g_h);
    cudaGetSymbolAddress((void**)&pq,   g_q);
    cudaGetSymbolAddress((void**)&pk,   g_k);
    cudaGetSymbolAddress((void**)&pv,   g_v);
    cudaGetSymbolAddress((void**)&pao,  g_ao);
    cudaGetSymbolAddress((void**)&px1,  g_x1);
    cudaGetSymbolAddress((void**)&ph2,  g_h2);
    cudaGetSymbolAddress((void**)&pmlp, g_mlp);

    cudaFuncSetAttribute(attn_mma,
        cudaFuncAttributeMaxDynamicSharedMemorySize, ATTN_SMEM_BYTES);
    cudaFuncSetAttribute(mma_gemm<0>,
        cudaFuncAttributeMaxDynamicSharedMemorySize, GEMM_SMEM);
    cudaFuncSetAttribute(mma_gemm<1>,
        cudaFuncAttributeMaxDynamicSharedMemorySize, GEMM_SMEM);
    cudaFuncSetAttribute(mma_gemm<2>,
        cudaFuncAttributeMaxDynamicSharedMemorySize, GEMM_SMEM);
    cudaFuncSetAttribute(mma_gemm<3>,
        cudaFuncAttributeMaxDynamicSharedMemorySize, GEMM_SMEM);

    // 1. LN1
    ln_kernel<<<M_, 256>>>(x, ln1g, ln1b, ph);

    // 2. QKV projections in ONE launch (z selects q/k/v)
    GOp oq = { Wq, bq, pq };
    GOp ok = { Wk, bk, pk };
    GOp ov = { Wv, bv, pv };
    mma_gemm<3><<<dim3(C_/128, M_/128, 3), 256, GEMM_SMEM>>>(ph, oq, ok, ov,
                                                             nullptr, M_, C_, C_);

    // 3. RoPE on q, k
    rope_kernel<<<(B_ * H_ * N_ * 32) / 256, 256>>>(pq, pk, rcos, rsin);

    // 4. Attention (tf32 mma)
    attn_mma<<<dim3(N_ / 128, B_ * H_), 256, ATTN_SMEM_BYTES>>>(pq, pk, pv, pao);

    // 5. O projection + residual -> x1
    GOp oo = { Wo, bo, px1 };
    mma_gemm<1><<<dim3(C_/128, M_/128, 1), 256, GEMM_SMEM>>>(pao, oo, oo, oo,
                                                             x, M_, C_, C_);

    // 6. LN2
    ln_kernel<<<M_, 256>>>(px1, ln2g, ln2b, ph2);

    // 7. MLP up + GELU
    GOp o1 = { W1, b1, pmlp };
    mma_gemm<2><<<dim3(F_/128, M_/128, 1), 256, GEMM_SMEM>>>(ph2, o1, o1, o1,
                                                             nullptr, M_, F_, C_);

    // 8. MLP down + residual -> out
    GOp o2 = { W2, b2, out };
    mma_gemm<1><<<dim3(C_/128, M_/128, 1), 256, GEMM_SMEM>>>(pmlp, o2, o2, o2,
                                                             px1, M_, C_, F_);
}